// round 3
// baseline (speedup 1.0000x reference)
#include <cuda_runtime.h>

#define N_NODES 16384
#define N_EDGES 32768
#define D 128
#define EDGE_DIM 10
#define EH 32
#define NCOLS (EH * D + D + D)   // 4096 (L) + 128 (l2 bias) + 128 (root) = 4352

// ---------------- scratch (static device globals; no allocation) ----------------
__device__ float g_Y[N_NODES * NCOLS];     // 285 MB: per-node precomputed x@[L|B|root]
__device__ float g_L1[D * NCOLS];
__device__ float g_L2[D * NCOLS];
__device__ float g_h1[N_EDGES * EH];
__device__ float g_h2[N_EDGES * EH];
__device__ float g_acc[N_NODES * D];
__device__ float g_cnt[N_NODES];
__device__ float g_x1[N_NODES * D];
__device__ float g_x2[N_NODES * D];
__device__ int   g_idx[2 * N_EDGES];       // normalized int32 src|dst
__device__ int   g_is64;

// ---------------- edge_index dtype detection + normalization ----------------
// If the buffer is genuinely int64, the first 128 int64 words are all in
// [0, N_NODES). If it is int32, consecutive pairs fuse into values >= 2^32
// (false-positive probability ~ (1/16384)^128 ~ 0).
__global__ void detect_idx(const long long* __restrict__ ei) {
    if (threadIdx.x == 0 && blockIdx.x == 0) {
        int ok = 1;
        for (int i = 0; i < 128; i++) {
            long long v = ei[i];
            if (v < 0 || v >= N_NODES) { ok = 0; break; }
        }
        g_is64 = ok;
    }
}

__global__ void convert_idx(const void* __restrict__ ei) {
    int i = blockIdx.x * blockDim.x + threadIdx.x;
    if (i >= 2 * N_EDGES) return;
    long long v = g_is64 ? ((const long long*)ei)[i]
                         : (long long)((const int*)ei)[i];
    int iv = (int)v;
    iv = iv < 0 ? 0 : (iv >= N_NODES ? N_NODES - 1 : iv);   // defensive clamp
    g_idx[i] = iv;
}

// ---------------- h = relu(edge_attr @ l1w + l1b) : [E, EH] ----------------
__global__ void build_h(const float* __restrict__ ea, const float* __restrict__ w,
                        const float* __restrict__ b, float* __restrict__ h) {
    int idx = blockIdx.x * blockDim.x + threadIdx.x;   // e*EH + j
    if (idx >= N_EDGES * EH) return;
    int e = idx >> 5, j = idx & 31;
    float s = b[j];
    const float* ear = ea + e * EDGE_DIM;
#pragma unroll
    for (int d = 0; d < EDGE_DIM; d++) s = fmaf(ear[d], w[d * EH + j], s);
    h[idx] = fmaxf(s, 0.f);
}

// ---------------- Lbig[i, c]: permuted l2w | l2 bias | root ----------------
__global__ void build_L(const float* __restrict__ l2w, const float* __restrict__ b_l2,
                        const float* __restrict__ root, float* __restrict__ L) {
    int idx = blockIdx.x * blockDim.x + threadIdx.x;   // i*NCOLS + c
    if (idx >= D * NCOLS) return;
    int i = idx / NCOLS, c = idx - i * NCOLS;
    float v;
    if (c < EH * D) {
        int k = c >> 7, o = c & 127;
        v = l2w[k * (D * D) + i * D + o];
    } else if (c < EH * D + D) {
        v = b_l2[i * D + (c - EH * D)];
    } else {
        v = root[i * D + (c - EH * D - D)];
    }
    L[idx] = v;
}

// ---------------- SGEMM: C[M=16384, N=4352] = A[M,128] @ B[128,N] ----------------
// 128x128 block tile, 8x8 per-thread microtile, BK=8, fp32.
__global__ void __launch_bounds__(256) sgemm_k128(const float* __restrict__ A,
                                                  const float* __restrict__ B,
                                                  float* __restrict__ C) {
    __shared__ float As[8][128];
    __shared__ float Bs[8][128];
    const int N = NCOLS;
    const int rowBase = blockIdx.y * 128;
    const int colBase = blockIdx.x * 128;
    const int tid = threadIdx.x;
    const int tm = (tid >> 4) * 8;
    const int tn = (tid & 15) * 8;

    const int arow = tid >> 1;              // 0..127
    const int ak   = (tid & 1) * 4;         // 0 or 4
    const int brow = tid >> 5;              // 0..7
    const int bcol = (tid & 31) * 4;        // 0..124

    float acc[8][8] = {};

    for (int kc = 0; kc < 128; kc += 8) {
        float4 av = *reinterpret_cast<const float4*>(&A[(rowBase + arow) * 128 + kc + ak]);
        *reinterpret_cast<float4*>(&Bs[brow][bcol]) =
            *reinterpret_cast<const float4*>(&B[(kc + brow) * N + colBase + bcol]);
        As[ak + 0][arow] = av.x;
        As[ak + 1][arow] = av.y;
        As[ak + 2][arow] = av.z;
        As[ak + 3][arow] = av.w;
        __syncthreads();
#pragma unroll
        for (int kk = 0; kk < 8; kk++) {
            float ra[8], rb[8];
            *reinterpret_cast<float4*>(ra)     = *reinterpret_cast<const float4*>(&As[kk][tm]);
            *reinterpret_cast<float4*>(ra + 4) = *reinterpret_cast<const float4*>(&As[kk][tm + 4]);
            *reinterpret_cast<float4*>(rb)     = *reinterpret_cast<const float4*>(&Bs[kk][tn]);
            *reinterpret_cast<float4*>(rb + 4) = *reinterpret_cast<const float4*>(&Bs[kk][tn + 4]);
#pragma unroll
            for (int i = 0; i < 8; i++)
#pragma unroll
                for (int j = 0; j < 8; j++)
                    acc[i][j] = fmaf(ra[i], rb[j], acc[i][j]);
        }
        __syncthreads();
    }

#pragma unroll
    for (int i = 0; i < 8; i++) {
        float* crow = &C[(rowBase + tm + i) * N + colBase + tn];
        *reinterpret_cast<float4*>(crow)     = make_float4(acc[i][0], acc[i][1], acc[i][2], acc[i][3]);
        *reinterpret_cast<float4*>(crow + 4) = make_float4(acc[i][4], acc[i][5], acc[i][6], acc[i][7]);
    }
}

// ---------------- zero accumulators ----------------
__global__ void zero_acc() {
    int idx = blockIdx.x * blockDim.x + threadIdx.x;
    if (idx < N_NODES * D) g_acc[idx] = 0.f;
    if (idx < N_NODES) g_cnt[idx] = 0.f;
}

// ---------------- edge message + scatter-add ----------------
// msg_e[o] = sum_k h[e,k] * Y[src, k*128+o] + Y[src, 4096+o]; atomic add into acc[dst].
__global__ void __launch_bounds__(256) edge_msg(const float* __restrict__ h,
                                                const float* __restrict__ Y) {
    const int half = threadIdx.x >> 7;
    const int e = blockIdx.x * 2 + half;
    const int o = threadIdx.x & 127;
    __shared__ float sh[2][EH];
    if (o < EH) sh[half][o] = h[e * EH + o];
    __syncthreads();
    const int src = g_idx[e];
    const int dst = g_idx[N_EDGES + e];
    const float* y = Y + (long long)src * NCOLS;
    float m = y[EH * D + o];                 // x_src @ l2_bias term
#pragma unroll
    for (int k = 0; k < EH; k++) m = fmaf(sh[half][k], y[k * D + o], m);
    atomicAdd(&g_acc[dst * D + o], m);
    if (o == 0) atomicAdd(&g_cnt[dst], 1.0f);
}

// ---------------- out = x@root + acc/max(cnt,1) + bias, optional relu ----------------
__global__ void combine(const float* __restrict__ Y, const float* __restrict__ bias,
                        float* __restrict__ out, int do_relu) {
    int idx = blockIdx.x * blockDim.x + threadIdx.x;
    if (idx >= N_NODES * D) return;
    int n = idx >> 7, o = idx & 127;
    float c = g_cnt[n];
    float v = Y[(long long)n * NCOLS + EH * D + D + o] + g_acc[idx] / fmaxf(c, 1.f) + bias[o];
    out[idx] = do_relu ? fmaxf(v, 0.f) : v;
}

// ---------------- launcher ----------------
extern "C" void kernel_launch(void* const* d_in, const int* in_sizes, int n_in,
                              void* d_out, int out_size) {
    const float* x       = (const float*)d_in[0];
    const void*  ei      = d_in[1];
    const float* ea      = (const float*)d_in[2];
    const float* w1_l1   = (const float*)d_in[3];
    const float* b1_l1   = (const float*)d_in[4];
    const float* w1_l2   = (const float*)d_in[5];
    const float* b1_l2   = (const float*)d_in[6];
    const float* w1_root = (const float*)d_in[7];
    const float* b1      = (const float*)d_in[8];
    const float* w2_l1   = (const float*)d_in[9];
    const float* b2_l1   = (const float*)d_in[10];
    const float* w2_l2   = (const float*)d_in[11];
    const float* b2_l2   = (const float*)d_in[12];
    const float* w2_root = (const float*)d_in[13];
    const float* b2      = (const float*)d_in[14];
    float*       out     = (float*)d_out;

    // Resolve device-global scratch addresses (query only; capture-safe).
    float *Y, *L1, *L2, *h1, *h2, *x1, *x2;
    cudaGetSymbolAddress((void**)&Y,  g_Y);
    cudaGetSymbolAddress((void**)&L1, g_L1);
    cudaGetSymbolAddress((void**)&L2, g_L2);
    cudaGetSymbolAddress((void**)&h1, g_h1);
    cudaGetSymbolAddress((void**)&h2, g_h2);
    cudaGetSymbolAddress((void**)&x1, g_x1);
    cudaGetSymbolAddress((void**)&x2, g_x2);

    // Normalize edge indices (handles int32-vs-int64 ambiguity).
    detect_idx<<<1, 32>>>((const long long*)ei);
    convert_idx<<<(2 * N_EDGES + 255) / 256, 256>>>(ei);

    // Edge MLP hidden activations (layer1 weights; layer2/3 share weights -> one h).
    build_h<<<(N_EDGES * EH + 255) / 256, 256>>>(ea, w1_l1, b1_l1, h1);
    build_h<<<(N_EDGES * EH + 255) / 256, 256>>>(ea, w2_l1, b2_l1, h2);
    // Combined weight matrices [128 x 4352]
    build_L<<<(D * NCOLS + 255) / 256, 256>>>(w1_l2, b1_l2, w1_root, L1);
    build_L<<<(D * NCOLS + 255) / 256, 256>>>(w2_l2, b2_l2, w2_root, L2);

    dim3 gGemm(NCOLS / 128, N_NODES / 128);
    const int zgrid = (N_NODES * D + 255) / 256;
    const int egrid = N_EDGES / 2;

    // ---- layer 1 ----
    zero_acc<<<zgrid, 256>>>();
    sgemm_k128<<<gGemm, 256>>>(x, L1, Y);
    edge_msg<<<egrid, 256>>>(h1, Y);
    combine<<<zgrid, 256>>>(Y, b1, x1, 1);
    // ---- layer 2 ----
    zero_acc<<<zgrid, 256>>>();
    sgemm_k128<<<gGemm, 256>>>(x1, L2, Y);
    edge_msg<<<egrid, 256>>>(h2, Y);
    combine<<<zgrid, 256>>>(Y, b2, x2, 1);
    // ---- layer 3 ----
    zero_acc<<<zgrid, 256>>>();
    sgemm_k128<<<gGemm, 256>>>(x2, L2, Y);
    edge_msg<<<egrid, 256>>>(h2, Y);
    combine<<<zgrid, 256>>>(Y, b2, out, 0);
}

// round 5
// speedup vs baseline: 1.8275x; 1.8275x over previous
#include <cuda_runtime.h>
#include <cuda_bf16.h>
#include <cstdint>

#define N_NODES 16384
#define N_EDGES 32768
#define D 128
#define EDGE_DIM 10
#define EH 32
#define NCOLS (EH * D + D + D)   // 4096 (L) + 128 (l2 bias) + 128 (root) = 4352
#define KS 384                   // split-K: A=[hi|hi|lo], B=[hi;lo;hi]
#define BM 128
#define BN 128

// ---------------- scratch (static device globals; no allocation) ----------------
__device__ float         g_Y[N_NODES * NCOLS];    // 285 MB
__device__ __nv_bfloat16 g_A3[N_NODES * KS];
__device__ __nv_bfloat16 g_B31[NCOLS * KS];
__device__ __nv_bfloat16 g_B32[NCOLS * KS];
__device__ float g_h1[N_EDGES * EH];
__device__ float g_h2[N_EDGES * EH];
__device__ float g_acc[N_NODES * D];
__device__ float g_cnt[N_NODES];
__device__ float g_x1[N_NODES * D];
__device__ float g_x2[N_NODES * D];
__device__ int   g_idx[2 * N_EDGES];
__device__ int   g_is64;

__device__ __forceinline__ uint32_t smem_u32(const void* p) {
    uint32_t a;
    asm("{ .reg .u64 t; cvta.to.shared.u64 t, %1; cvt.u32.u64 %0, t; }" : "=r"(a) : "l"(p));
    return a;
}

// ---------------- edge_index dtype detection + normalization ----------------
__global__ void detect_idx(const long long* __restrict__ ei) {
    if (threadIdx.x == 0 && blockIdx.x == 0) {
        int ok = 1;
        for (int i = 0; i < 128; i++) {
            long long v = ei[i];
            if (v < 0 || v >= N_NODES) { ok = 0; break; }
        }
        g_is64 = ok;
    }
}
__global__ void convert_idx(const void* __restrict__ ei) {
    int i = blockIdx.x * blockDim.x + threadIdx.x;
    if (i >= 2 * N_EDGES) return;
    long long v = g_is64 ? ((const long long*)ei)[i] : (long long)((const int*)ei)[i];
    int iv = (int)v;
    iv = iv < 0 ? 0 : (iv >= N_NODES ? N_NODES - 1 : iv);
    g_idx[i] = iv;
}

// ---------------- h = relu(edge_attr @ l1w + l1b) ----------------
__global__ void build_h(const float* __restrict__ ea, const float* __restrict__ w,
                        const float* __restrict__ b, float* __restrict__ h) {
    int idx = blockIdx.x * blockDim.x + threadIdx.x;
    if (idx >= N_EDGES * EH) return;
    int e = idx >> 5, j = idx & 31;
    float s = b[j];
    const float* ear = ea + e * EDGE_DIM;
#pragma unroll
    for (int d = 0; d < EDGE_DIM; d++) s = fmaf(ear[d], w[d * EH + j], s);
    h[idx] = fmaxf(s, 0.f);
}

// ---------------- split-bf16 conversion of A ----------------
__global__ void convA(const float* __restrict__ X, __nv_bfloat16* __restrict__ A3) {
    int idx = blockIdx.x * blockDim.x + threadIdx.x;
    if (idx >= N_NODES * D) return;
    int r = idx >> 7, c = idx & 127;
    float v = X[idx];
    __nv_bfloat16 hi = __float2bfloat16(v);
    __nv_bfloat16 lo = __float2bfloat16(v - __bfloat162float(hi));
    __nv_bfloat16* row = A3 + (size_t)r * KS;
    row[c] = hi; row[c + 128] = hi; row[c + 256] = lo;
}

// ---------------- B'[n, k] (K-major): permuted l2w | l2 bias | root, split ----------------
__global__ void buildB(const float* __restrict__ l2w, const float* __restrict__ b_l2,
                       const float* __restrict__ root, __nv_bfloat16* __restrict__ B3) {
    int idx = blockIdx.x * blockDim.x + threadIdx.x;   // n*128 + k
    if (idx >= NCOLS * D) return;
    int n = idx >> 7, k = idx & 127;
    float v;
    if (n < EH * D)            v = l2w[(n >> 7) * (D * D) + k * D + (n & 127)];
    else if (n < EH * D + D)   v = b_l2[k * D + (n - EH * D)];
    else                       v = root[k * D + (n - EH * D - D)];
    __nv_bfloat16 hi = __float2bfloat16(v);
    __nv_bfloat16 lo = __float2bfloat16(v - __bfloat162float(hi));
    __nv_bfloat16* row = B3 + (size_t)n * KS;
    row[k] = hi; row[k + 128] = lo; row[k + 256] = hi;
}

// ---------------- HMMA GEMM: C[16384 x 4352] = A'[.,384] @ B'^T ----------------
// CTA: BM=128 x BN=128, BK=64. 8 warps, warp tile 64x32 via mma.sync.m16n8k16.
__global__ void __launch_bounds__(256) gemm_mma(const __nv_bfloat16* __restrict__ A,
                                                const __nv_bfloat16* __restrict__ B,
                                                float* __restrict__ C) {
    __shared__ __align__(1024) char sA[BM * 128];   // 128 rows x 64 bf16 (128B), swizzled
    __shared__ __align__(1024) char sB[BN * 128];
    const int tid = threadIdx.x, lane = tid & 31, wid = tid >> 5;
    const int warp_m = wid & 1, warp_n = wid >> 1;       // 2 x 4
    const int rowBase = blockIdx.y * BM;
    const int colBase = blockIdx.x * BN;
    const uint32_t aB = smem_u32(sA), bB = smem_u32(sB);
    const char* Ab = (const char*)A;
    const char* Bb = (const char*)B;

    float acc[4][4][4];
#pragma unroll
    for (int i = 0; i < 4; i++)
#pragma unroll
        for (int j = 0; j < 4; j++)
#pragma unroll
            for (int r = 0; r < 4; r++) acc[i][j][r] = 0.f;

    // per-thread gmem->smem mapping: 4 x 16B each for A and B
    const int ldr = tid >> 3;            // 0..31 (+32 per iter)
    const int ldc = tid & 7;             // 16B unit within 128B row

    for (int ch = 0; ch < 6; ch++) {
        __syncthreads();
#pragma unroll
        for (int i = 0; i < 4; i++) {
            int r = ldr + i * 32;
            uint32_t soff = (uint32_t)(r * 128 + ((ldc * 16) ^ ((r & 7) * 16)));
            *(uint4*)(sA + soff) =
                *(const uint4*)(Ab + (size_t)(rowBase + r) * (KS * 2) + ch * 128 + ldc * 16);
            *(uint4*)(sB + soff) =
                *(const uint4*)(Bb + (size_t)(colBase + r) * (KS * 2) + ch * 128 + ldc * 16);
        }
        __syncthreads();

#pragma unroll
        for (int s = 0; s < 4; s++) {                    // 4 x k16 within the 64-k chunk
            uint32_t af[4][4], bf[4][2];
#pragma unroll
            for (int i = 0; i < 4; i++) {
                int row = warp_m * 64 + i * 16 + (lane & 15);
                int kb = s * 32 + ((lane >> 4) << 4);
                uint32_t addr = aB + row * 128 + (kb ^ ((row & 7) * 16));
                asm volatile("ldmatrix.sync.aligned.m8n8.x4.shared.b16 {%0,%1,%2,%3}, [%4];"
                             : "=r"(af[i][0]), "=r"(af[i][1]), "=r"(af[i][2]), "=r"(af[i][3])
                             : "r"(addr));
            }
#pragma unroll
            for (int j = 0; j < 4; j++) {
                int nrow = warp_n * 32 + j * 8 + (lane & 7);
                int kb = s * 32 + (((lane >> 3) & 1) << 4);
                uint32_t addr = bB + nrow * 128 + (kb ^ ((nrow & 7) * 16));
                asm volatile("ldmatrix.sync.aligned.m8n8.x2.shared.b16 {%0,%1}, [%2];"
                             : "=r"(bf[j][0]), "=r"(bf[j][1]) : "r"(addr));
            }
#pragma unroll
            for (int i = 0; i < 4; i++)
#pragma unroll
                for (int j = 0; j < 4; j++)
                    asm volatile(
                        "mma.sync.aligned.m16n8k16.row.col.f32.bf16.bf16.f32 "
                        "{%0,%1,%2,%3}, {%4,%5,%6,%7}, {%8,%9}, {%0,%1,%2,%3};"
                        : "+f"(acc[i][j][0]), "+f"(acc[i][j][1]),
                          "+f"(acc[i][j][2]), "+f"(acc[i][j][3])
                        : "r"(af[i][0]), "r"(af[i][1]), "r"(af[i][2]), "r"(af[i][3]),
                          "r"(bf[j][0]), "r"(bf[j][1]));
        }
    }

    // Epilogue: direct float2 stores (32B-contiguous per 4 lanes)
#pragma unroll
    for (int i = 0; i < 4; i++) {
        int r0 = rowBase + warp_m * 64 + i * 16 + (lane >> 2);
#pragma unroll
        for (int j = 0; j < 4; j++) {
            int col = colBase + warp_n * 32 + j * 8 + (lane & 3) * 2;
            *(float2*)&C[(size_t)r0 * NCOLS + col]       = make_float2(acc[i][j][0], acc[i][j][1]);
            *(float2*)&C[(size_t)(r0 + 8) * NCOLS + col] = make_float2(acc[i][j][2], acc[i][j][3]);
        }
    }
}

// ---------------- zero accumulators ----------------
__global__ void zero_acc() {
    int idx = blockIdx.x * blockDim.x + threadIdx.x;
    if (idx < N_NODES * D) g_acc[idx] = 0.f;
    if (idx < N_NODES) g_cnt[idx] = 0.f;
}

// ---------------- edge message + scatter-add ----------------
__global__ void __launch_bounds__(256) edge_msg(const float* __restrict__ h,
                                                const float* __restrict__ Y) {
    const int half = threadIdx.x >> 7;
    const int e = blockIdx.x * 2 + half;
    const int o = threadIdx.x & 127;
    __shared__ float sh[2][EH];
    if (o < EH) sh[half][o] = h[e * EH + o];
    __syncthreads();
    const int src = g_idx[e];
    const int dst = g_idx[N_EDGES + e];
    const float* y = Y + (size_t)src * NCOLS;
    float m = y[EH * D + o];
#pragma unroll
    for (int k = 0; k < EH; k++) m = fmaf(sh[half][k], y[k * D + o], m);
    atomicAdd(&g_acc[dst * D + o], m);
    if (o == 0) atomicAdd(&g_cnt[dst], 1.0f);
}

// ---------------- out = x@root + acc/max(cnt,1) + bias, optional relu ----------------
__global__ void combine(const float* __restrict__ Y, const float* __restrict__ bias,
                        float* __restrict__ out, int do_relu) {
    int idx = blockIdx.x * blockDim.x + threadIdx.x;
    if (idx >= N_NODES * D) return;
    int n = idx >> 7, o = idx & 127;
    float c = g_cnt[n];
    float v = Y[(size_t)n * NCOLS + EH * D + D + o] + g_acc[idx] / fmaxf(c, 1.f) + bias[o];
    out[idx] = do_relu ? fmaxf(v, 0.f) : v;
}

// ---------------- launcher ----------------
extern "C" void kernel_launch(void* const* d_in, const int* in_sizes, int n_in,
                              void* d_out, int out_size) {
    const float* x       = (const float*)d_in[0];
    const void*  ei      = d_in[1];
    const float* ea      = (const float*)d_in[2];
    const float* w1_l1   = (const float*)d_in[3];
    const float* b1_l1   = (const float*)d_in[4];
    const float* w1_l2   = (const float*)d_in[5];
    const float* b1_l2   = (const float*)d_in[6];
    const float* w1_root = (const float*)d_in[7];
    const float* b1      = (const float*)d_in[8];
    const float* w2_l1   = (const float*)d_in[9];
    const float* b2_l1   = (const float*)d_in[10];
    const float* w2_l2   = (const float*)d_in[11];
    const float* b2_l2   = (const float*)d_in[12];
    const float* w2_root = (const float*)d_in[13];
    const float* b2      = (const float*)d_in[14];
    float*       out     = (float*)d_out;

    float *Y, *h1, *h2, *x1, *x2;
    __nv_bfloat16 *A3, *B31, *B32;
    cudaGetSymbolAddress((void**)&Y,   g_Y);
    cudaGetSymbolAddress((void**)&A3,  g_A3);
    cudaGetSymbolAddress((void**)&B31, g_B31);
    cudaGetSymbolAddress((void**)&B32, g_B32);
    cudaGetSymbolAddress((void**)&h1,  g_h1);
    cudaGetSymbolAddress((void**)&h2,  g_h2);
    cudaGetSymbolAddress((void**)&x1,  g_x1);
    cudaGetSymbolAddress((void**)&x2,  g_x2);

    detect_idx<<<1, 32>>>((const long long*)ei);
    convert_idx<<<(2 * N_EDGES + 255) / 256, 256>>>(ei);
    build_h<<<(N_EDGES * EH + 255) / 256, 256>>>(ea, w1_l1, b1_l1, h1);
    build_h<<<(N_EDGES * EH + 255) / 256, 256>>>(ea, w2_l1, b2_l1, h2);
    buildB<<<(NCOLS * D + 255) / 256, 256>>>(w1_l2, b1_l2, w1_root, B31);
    buildB<<<(NCOLS * D + 255) / 256, 256>>>(w2_l2, b2_l2, w2_root, B32);

    dim3 gGemm(NCOLS / BN, N_NODES / BM);               // (34, 128)
    const int zgrid = (N_NODES * D + 255) / 256;
    const int egrid = N_EDGES / 2;

    // ---- layer 1 ----
    convA<<<zgrid, 256>>>(x, A3);
    zero_acc<<<zgrid, 256>>>();
    gemm_mma<<<gGemm, 256>>>(A3, B31, Y);
    edge_msg<<<egrid, 256>>>(h1, Y);
    combine<<<zgrid, 256>>>(Y, b1, x1, 1);
    // ---- layer 2 ----
    convA<<<zgrid, 256>>>(x1, A3);
    zero_acc<<<zgrid, 256>>>();
    gemm_mma<<<gGemm, 256>>>(A3, B32, Y);
    edge_msg<<<egrid, 256>>>(h2, Y);
    combine<<<zgrid, 256>>>(Y, b2, x2, 1);
    // ---- layer 3 ----
    convA<<<zgrid, 256>>>(x2, A3);
    zero_acc<<<zgrid, 256>>>();
    gemm_mma<<<gGemm, 256>>>(A3, B32, Y);
    edge_msg<<<egrid, 256>>>(h2, Y);
    combine<<<zgrid, 256>>>(Y, b2, out, 0);
}

// round 6
// speedup vs baseline: 2.0709x; 1.1332x over previous
#include <cuda_runtime.h>
#include <cuda_bf16.h>
#include <cstdint>

#define N_NODES 16384
#define N_EDGES 32768
#define D 128
#define EDGE_DIM 10
#define EH 32
#define NCOLS (EH * D + D + D)   // 4096 (L) + 128 (l2 bias) + 128 (root) = 4352
#define KS 384                   // split-K: A=[hi|hi|lo], B=[hi;lo;hi]
#define BM 128
#define BN 128
#define STAGE_BYTES (BM * 128 + BN * 128)   // 32 KB per stage

// ---------------- scratch (static device globals; no allocation) ----------------
__device__ float         g_Y[N_NODES * NCOLS];    // 285 MB
__device__ __nv_bfloat16 g_A3[N_NODES * KS];
__device__ __nv_bfloat16 g_B31[NCOLS * KS];
__device__ __nv_bfloat16 g_B32[NCOLS * KS];
__device__ float g_h1[N_EDGES * EH];
__device__ float g_h2[N_EDGES * EH];
__device__ float g_acc[N_NODES * D];
__device__ float g_cnt[N_NODES];
__device__ int   g_idx[2 * N_EDGES];
__device__ int   g_is64;
// edge sort-by-src
__device__ int g_srcCount[N_NODES];
__device__ int g_srcOff[N_NODES];
__device__ int g_rank[N_EDGES];
__device__ int g_perm[N_EDGES];

__device__ __forceinline__ uint32_t smem_u32(const void* p) {
    uint32_t a;
    asm("{ .reg .u64 t; cvta.to.shared.u64 t, %1; cvt.u32.u64 %0, t; }" : "=r"(a) : "l"(p));
    return a;
}
#define CP_ASYNC16(saddr, gptr) \
    asm volatile("cp.async.cg.shared.global [%0], [%1], 16;" :: "r"(saddr), "l"(gptr))
#define CP_COMMIT() asm volatile("cp.async.commit_group;" ::: "memory")
#define CP_WAIT0()  asm volatile("cp.async.wait_group 0;" ::: "memory")

// ---------------- edge_index dtype detection + normalization ----------------
__global__ void detect_idx(const long long* __restrict__ ei) {
    if (threadIdx.x == 0 && blockIdx.x == 0) {
        int ok = 1;
        for (int i = 0; i < 128; i++) {
            long long v = ei[i];
            if (v < 0 || v >= N_NODES) { ok = 0; break; }
        }
        g_is64 = ok;
    }
}
__global__ void convert_idx(const void* __restrict__ ei) {
    int i = blockIdx.x * blockDim.x + threadIdx.x;
    if (i >= 2 * N_EDGES) return;
    long long v = g_is64 ? ((const long long*)ei)[i] : (long long)((const int*)ei)[i];
    int iv = (int)v;
    iv = iv < 0 ? 0 : (iv >= N_NODES ? N_NODES - 1 : iv);
    g_idx[i] = iv;
}

// ---------------- edge sorting by src + one-time dst counts ----------------
__global__ void zero_setup() {
    int i = blockIdx.x * blockDim.x + threadIdx.x;
    if (i < N_NODES) { g_srcCount[i] = 0; g_cnt[i] = 0.f; }
}
__global__ void count_edges() {
    int e = blockIdx.x * blockDim.x + threadIdx.x;
    if (e >= N_EDGES) return;
    g_rank[e] = atomicAdd(&g_srcCount[g_idx[e]], 1);
    atomicAdd(&g_cnt[g_idx[N_EDGES + e]], 1.0f);
}
__global__ void scan_counts() {          // 1 block, 1024 threads, 16 elems each
    __shared__ int part[1024];
    int t = threadIdx.x;
    int base = t * 16;
    int local[16];
    int s = 0;
#pragma unroll
    for (int i = 0; i < 16; i++) { local[i] = s; s += g_srcCount[base + i]; }
    part[t] = s;
    __syncthreads();
    for (int off = 1; off < 1024; off <<= 1) {
        int v = (t >= off) ? part[t - off] : 0;
        __syncthreads();
        part[t] += v;
        __syncthreads();
    }
    int pre = (t == 0) ? 0 : part[t - 1];
#pragma unroll
    for (int i = 0; i < 16; i++) g_srcOff[base + i] = pre + local[i];
}
__global__ void place_edges() {
    int e = blockIdx.x * blockDim.x + threadIdx.x;
    if (e >= N_EDGES) return;
    g_perm[g_srcOff[g_idx[e]] + g_rank[e]] = e;
}

// ---------------- h = relu(edge_attr @ l1w + l1b) ----------------
__global__ void build_h(const float* __restrict__ ea, const float* __restrict__ w,
                        const float* __restrict__ b, float* __restrict__ h) {
    int idx = blockIdx.x * blockDim.x + threadIdx.x;
    if (idx >= N_EDGES * EH) return;
    int e = idx >> 5, j = idx & 31;
    float s = b[j];
    const float* ear = ea + e * EDGE_DIM;
#pragma unroll
    for (int d = 0; d < EDGE_DIM; d++) s = fmaf(ear[d], w[d * EH + j], s);
    h[idx] = fmaxf(s, 0.f);
}

// ---------------- split-bf16 conversion of A (layer-1 input only) ----------------
__global__ void convA(const float* __restrict__ X, __nv_bfloat16* __restrict__ A3) {
    int idx = blockIdx.x * blockDim.x + threadIdx.x;
    if (idx >= N_NODES * D) return;
    int r = idx >> 7, c = idx & 127;
    float v = X[idx];
    __nv_bfloat16 hi = __float2bfloat16(v);
    __nv_bfloat16 lo = __float2bfloat16(v - __bfloat162float(hi));
    __nv_bfloat16* row = A3 + (size_t)r * KS;
    row[c] = hi; row[c + 128] = hi; row[c + 256] = lo;
}

// ---------------- B'[n, k] (K-major): permuted l2w | l2 bias | root, split ----------------
__global__ void buildB(const float* __restrict__ l2w, const float* __restrict__ b_l2,
                       const float* __restrict__ root, __nv_bfloat16* __restrict__ B3) {
    int idx = blockIdx.x * blockDim.x + threadIdx.x;   // n*128 + k
    if (idx >= NCOLS * D) return;
    int n = idx >> 7, k = idx & 127;
    float v;
    if (n < EH * D)            v = l2w[(n >> 7) * (D * D) + k * D + (n & 127)];
    else if (n < EH * D + D)   v = b_l2[k * D + (n - EH * D)];
    else                       v = root[k * D + (n - EH * D - D)];
    __nv_bfloat16 hi = __float2bfloat16(v);
    __nv_bfloat16 lo = __float2bfloat16(v - __bfloat162float(hi));
    __nv_bfloat16* row = B3 + (size_t)n * KS;
    row[k] = hi; row[k + 128] = lo; row[k + 256] = hi;
}

// ---------------- HMMA GEMM (cp.async double-buffered) ----------------
// C[16384 x 4352] = A'[.,384] @ B'^T. CTA 128x128, BK=64, 8 warps (64x32 each).
__global__ void __launch_bounds__(256) gemm_mma(const __nv_bfloat16* __restrict__ A,
                                                const __nv_bfloat16* __restrict__ B,
                                                float* __restrict__ C) {
    extern __shared__ __align__(1024) char smem[];
    const int tid = threadIdx.x, lane = tid & 31, wid = tid >> 5;
    const int warp_m = wid & 1, warp_n = wid >> 1;       // 2 x 4
    const int rowBase = blockIdx.y * BM;
    const int colBase = blockIdx.x * BN;
    const uint32_t smemU = smem_u32(smem);
    const char* Ab = (const char*)A;
    const char* Bb = (const char*)B;

    float acc[4][4][4];
#pragma unroll
    for (int i = 0; i < 4; i++)
#pragma unroll
        for (int j = 0; j < 4; j++)
#pragma unroll
            for (int r = 0; r < 4; r++) acc[i][j][r] = 0.f;

    const int ldr = tid >> 3;            // row 0..31 (+32 per i)
    const int ldc = tid & 7;             // 16B unit within 128B row

    // ---- stage loader (cp.async, 8 x 16B per thread) ----
    auto load_stage = [&](int st, int ch) {
        uint32_t sa = smemU + st * STAGE_BYTES;
        uint32_t sb = sa + BM * 128;
#pragma unroll
        for (int i = 0; i < 4; i++) {
            int r = ldr + i * 32;
            uint32_t soff = (uint32_t)(r * 128 + ((ldc * 16) ^ ((r & 7) * 16)));
            CP_ASYNC16(sa + soff, Ab + (size_t)(rowBase + r) * (KS * 2) + ch * 128 + ldc * 16);
            CP_ASYNC16(sb + soff, Bb + (size_t)(colBase + r) * (KS * 2) + ch * 128 + ldc * 16);
        }
        CP_COMMIT();
    };

    load_stage(0, 0);

    for (int ch = 0; ch < 6; ch++) {
        CP_WAIT0();
        __syncthreads();
        if (ch < 5) load_stage((ch + 1) & 1, ch + 1);

        const uint32_t aB = smemU + (ch & 1) * STAGE_BYTES;
        const uint32_t bB = aB + BM * 128;
#pragma unroll
        for (int s = 0; s < 4; s++) {                    // 4 x k16 within chunk
            uint32_t af[4][4], bf[4][2];
#pragma unroll
            for (int i = 0; i < 4; i++) {
                int row = warp_m * 64 + i * 16 + (lane & 15);
                int kb = s * 32 + ((lane >> 4) << 4);
                uint32_t addr = aB + row * 128 + (kb ^ ((row & 7) * 16));
                asm volatile("ldmatrix.sync.aligned.m8n8.x4.shared.b16 {%0,%1,%2,%3}, [%4];"
                             : "=r"(af[i][0]), "=r"(af[i][1]), "=r"(af[i][2]), "=r"(af[i][3])
                             : "r"(addr));
            }
#pragma unroll
            for (int j = 0; j < 4; j++) {
                int nrow = warp_n * 32 + j * 8 + (lane & 7);
                int kb = s * 32 + (((lane >> 3) & 1) << 4);
                uint32_t addr = bB + nrow * 128 + (kb ^ ((nrow & 7) * 16));
                asm volatile("ldmatrix.sync.aligned.m8n8.x2.shared.b16 {%0,%1}, [%2];"
                             : "=r"(bf[j][0]), "=r"(bf[j][1]) : "r"(addr));
            }
#pragma unroll
            for (int i = 0; i < 4; i++)
#pragma unroll
                for (int j = 0; j < 4; j++)
                    asm volatile(
                        "mma.sync.aligned.m16n8k16.row.col.f32.bf16.bf16.f32 "
                        "{%0,%1,%2,%3}, {%4,%5,%6,%7}, {%8,%9}, {%0,%1,%2,%3};"
                        : "+f"(acc[i][j][0]), "+f"(acc[i][j][1]),
                          "+f"(acc[i][j][2]), "+f"(acc[i][j][3])
                        : "r"(af[i][0]), "r"(af[i][1]), "r"(af[i][2]), "r"(af[i][3]),
                          "r"(bf[j][0]), "r"(bf[j][1]));
        }
        __syncthreads();
    }

    // Epilogue: direct float2 stores
#pragma unroll
    for (int i = 0; i < 4; i++) {
        int r0 = rowBase + warp_m * 64 + i * 16 + (lane >> 2);
#pragma unroll
        for (int j = 0; j < 4; j++) {
            int col = colBase + warp_n * 32 + j * 8 + (lane & 3) * 2;
            *(float2*)&C[(size_t)r0 * NCOLS + col]       = make_float2(acc[i][j][0], acc[i][j][1]);
            *(float2*)&C[(size_t)(r0 + 8) * NCOLS + col] = make_float2(acc[i][j][2], acc[i][j][3]);
        }
    }
}

// ---------------- zero acc ----------------
__global__ void zero_acc() {
    int idx = blockIdx.x * blockDim.x + threadIdx.x;
    if (idx < N_NODES * D) g_acc[idx] = 0.f;
}

// ---------------- edge message (src-sorted) + scatter-add ----------------
__global__ void __launch_bounds__(256) edge_msg(const float* __restrict__ h,
                                                const float* __restrict__ Y) {
    const int half = threadIdx.x >> 7;
    const int slot = blockIdx.x * 2 + half;
    const int o = threadIdx.x & 127;
    __shared__ float sh[2][EH];
    __shared__ int se[2];
    if (o == 0) se[half] = g_perm[slot];
    __syncthreads();
    const int eo = se[half];
    if (o < EH) sh[half][o] = h[eo * EH + o];
    __syncthreads();
    const int src = g_idx[eo];
    const int dst = g_idx[N_EDGES + eo];
    const float* y = Y + (size_t)src * NCOLS;
    float m = y[EH * D + o];
#pragma unroll
    for (int k = 0; k < EH; k++) m = fmaf(sh[half][k], y[k * D + o], m);
    atomicAdd(&g_acc[dst * D + o], m);
}

// ---------------- combine: out = Yroot + acc/max(cnt,1) + bias; emit fp32 or split-A3 ----------------
__global__ void combine(const float* __restrict__ Y, const float* __restrict__ bias,
                        float* __restrict__ outf, __nv_bfloat16* __restrict__ A3,
                        int do_relu) {
    int idx = blockIdx.x * blockDim.x + threadIdx.x;
    if (idx >= N_NODES * D) return;
    int n = idx >> 7, o = idx & 127;
    float v = Y[(size_t)n * NCOLS + EH * D + D + o] + g_acc[idx] / fmaxf(g_cnt[n], 1.f) + bias[o];
    if (do_relu) v = fmaxf(v, 0.f);
    if (outf) outf[idx] = v;
    if (A3) {
        __nv_bfloat16 hi = __float2bfloat16(v);
        __nv_bfloat16 lo = __float2bfloat16(v - __bfloat162float(hi));
        __nv_bfloat16* row = A3 + (size_t)n * KS;
        row[o] = hi; row[o + 128] = hi; row[o + 256] = lo;
    }
}

// ---------------- launcher ----------------
extern "C" void kernel_launch(void* const* d_in, const int* in_sizes, int n_in,
                              void* d_out, int out_size) {
    const float* x       = (const float*)d_in[0];
    const void*  ei      = d_in[1];
    const float* ea      = (const float*)d_in[2];
    const float* w1_l1   = (const float*)d_in[3];
    const float* b1_l1   = (const float*)d_in[4];
    const float* w1_l2   = (const float*)d_in[5];
    const float* b1_l2   = (const float*)d_in[6];
    const float* w1_root = (const float*)d_in[7];
    const float* b1      = (const float*)d_in[8];
    const float* w2_l1   = (const float*)d_in[9];
    const float* b2_l1   = (const float*)d_in[10];
    const float* w2_l2   = (const float*)d_in[11];
    const float* b2_l2   = (const float*)d_in[12];
    const float* w2_root = (const float*)d_in[13];
    const float* b2      = (const float*)d_in[14];
    float*       out     = (float*)d_out;

    float *Y, *h1, *h2;
    __nv_bfloat16 *A3, *B31, *B32;
    cudaGetSymbolAddress((void**)&Y,   g_Y);
    cudaGetSymbolAddress((void**)&A3,  g_A3);
    cudaGetSymbolAddress((void**)&B31, g_B31);
    cudaGetSymbolAddress((void**)&B32, g_B32);
    cudaGetSymbolAddress((void**)&h1,  g_h1);
    cudaGetSymbolAddress((void**)&h2,  g_h2);

    const int SMEM_GEMM = 2 * STAGE_BYTES;              // 64 KB
    cudaFuncSetAttribute(gemm_mma, cudaFuncAttributeMaxDynamicSharedMemorySize, SMEM_GEMM);

    // ---- setup (indices, sort, edge MLP, weights) ----
    detect_idx<<<1, 32>>>((const long long*)ei);
    convert_idx<<<(2 * N_EDGES + 255) / 256, 256>>>(ei);
    zero_setup<<<(N_NODES + 255) / 256, 256>>>();
    count_edges<<<(N_EDGES + 255) / 256, 256>>>();
    scan_counts<<<1, 1024>>>();
    place_edges<<<(N_EDGES + 255) / 256, 256>>>();
    build_h<<<(N_EDGES * EH + 255) / 256, 256>>>(ea, w1_l1, b1_l1, h1);
    build_h<<<(N_EDGES * EH + 255) / 256, 256>>>(ea, w2_l1, b2_l1, h2);
    buildB<<<(NCOLS * D + 255) / 256, 256>>>(w1_l2, b1_l2, w1_root, B31);
    buildB<<<(NCOLS * D + 255) / 256, 256>>>(w2_l2, b2_l2, w2_root, B32);

    dim3 gGemm(NCOLS / BN, N_NODES / BM);               // (34, 128)
    const int zgrid = (N_NODES * D + 255) / 256;
    const int egrid = N_EDGES / 2;

    // ---- layer 1 ----
    convA<<<zgrid, 256>>>(x, A3);
    zero_acc<<<zgrid, 256>>>();
    gemm_mma<<<gGemm, 256, SMEM_GEMM>>>(A3, B31, Y);
    edge_msg<<<egrid, 256>>>(h1, Y);
    combine<<<zgrid, 256>>>(Y, b1, nullptr, A3, 1);
    // ---- layer 2 ----
    zero_acc<<<zgrid, 256>>>();
    gemm_mma<<<gGemm, 256, SMEM_GEMM>>>(A3, B32, Y);
    edge_msg<<<egrid, 256>>>(h2, Y);
    combine<<<zgrid, 256>>>(Y, b2, nullptr, A3, 1);
    // ---- layer 3 ----
    zero_acc<<<zgrid, 256>>>();
    gemm_mma<<<gGemm, 256, SMEM_GEMM>>>(A3, B32, Y);
    edge_msg<<<egrid, 256>>>(h2, Y);
    combine<<<zgrid, 256>>>(Y, b2, out, nullptr, 0);
}

// round 7
// speedup vs baseline: 2.3587x; 1.1390x over previous
#include <cuda_runtime.h>
#include <cuda_bf16.h>
#include <cuda_fp16.h>
#include <cstdint>

#define N_NODES 16384
#define N_EDGES 32768
#define D 128
#define EDGE_DIM 10
#define EH 32
#define NCOLS (EH * D + D + D)   // 4096 (L) + 128 (l2 bias) + 128 (root) = 4352
#define KS 384                   // split-K: A=[hi|hi|lo], B=[hi;lo;hi]
#define BM 128
#define BN 128
#define STAGE_BYTES (BM * 128 + BN * 128)   // 32 KB per stage

// ---------------- scratch (static device globals; no allocation) ----------------
__device__ __half        g_Y[N_NODES * NCOLS];    // 142 MB (fp16 Y)
__device__ __nv_bfloat16 g_A3[N_NODES * KS];
__device__ __nv_bfloat16 g_B31[NCOLS * KS];
__device__ __nv_bfloat16 g_B32[NCOLS * KS];
__device__ float g_h1[N_EDGES * EH];
__device__ float g_h2[N_EDGES * EH];
__device__ float g_acc[N_NODES * D];
__device__ float g_cnt[N_NODES];
__device__ int   g_idx[2 * N_EDGES];
__device__ int   g_is64;
// edge sort-by-src
__device__ int g_srcCount[N_NODES];
__device__ int g_srcOff[N_NODES];
__device__ int g_rank[N_EDGES];
__device__ int g_perm[N_EDGES];

__device__ __forceinline__ uint32_t smem_u32(const void* p) {
    uint32_t a;
    asm("{ .reg .u64 t; cvta.to.shared.u64 t, %1; cvt.u32.u64 %0, t; }" : "=r"(a) : "l"(p));
    return a;
}
#define CP_ASYNC16(saddr, gptr) \
    asm volatile("cp.async.cg.shared.global [%0], [%1], 16;" :: "r"(saddr), "l"(gptr))
#define CP_COMMIT() asm volatile("cp.async.commit_group;" ::: "memory")
#define CP_WAIT0()  asm volatile("cp.async.wait_group 0;" ::: "memory")

// ---------------- edge_index dtype detection + normalization ----------------
__global__ void detect_idx(const long long* __restrict__ ei) {
    if (threadIdx.x == 0 && blockIdx.x == 0) {
        int ok = 1;
        for (int i = 0; i < 128; i++) {
            long long v = ei[i];
            if (v < 0 || v >= N_NODES) { ok = 0; break; }
        }
        g_is64 = ok;
    }
}
__global__ void convert_idx(const void* __restrict__ ei) {
    int i = blockIdx.x * blockDim.x + threadIdx.x;
    if (i >= 2 * N_EDGES) return;
    long long v = g_is64 ? ((const long long*)ei)[i] : (long long)((const int*)ei)[i];
    int iv = (int)v;
    iv = iv < 0 ? 0 : (iv >= N_NODES ? N_NODES - 1 : iv);
    g_idx[i] = iv;
}

// ---------------- edge sorting by src + one-time dst counts ----------------
__global__ void zero_setup() {
    int i = blockIdx.x * blockDim.x + threadIdx.x;
    if (i < N_NODES) { g_srcCount[i] = 0; g_cnt[i] = 0.f; }
}
__global__ void count_edges() {
    int e = blockIdx.x * blockDim.x + threadIdx.x;
    if (e >= N_EDGES) return;
    g_rank[e] = atomicAdd(&g_srcCount[g_idx[e]], 1);
    atomicAdd(&g_cnt[g_idx[N_EDGES + e]], 1.0f);
}
__global__ void scan_counts() {          // 1 block, 1024 threads, 16 elems each
    __shared__ int part[1024];
    int t = threadIdx.x;
    int base = t * 16;
    int local[16];
    int s = 0;
#pragma unroll
    for (int i = 0; i < 16; i++) { local[i] = s; s += g_srcCount[base + i]; }
    part[t] = s;
    __syncthreads();
    for (int off = 1; off < 1024; off <<= 1) {
        int v = (t >= off) ? part[t - off] : 0;
        __syncthreads();
        part[t] += v;
        __syncthreads();
    }
    int pre = (t == 0) ? 0 : part[t - 1];
#pragma unroll
    for (int i = 0; i < 16; i++) g_srcOff[base + i] = pre + local[i];
}
__global__ void place_edges() {
    int e = blockIdx.x * blockDim.x + threadIdx.x;
    if (e >= N_EDGES) return;
    g_perm[g_srcOff[g_idx[e]] + g_rank[e]] = e;
}

// ---------------- h = relu(edge_attr @ l1w + l1b) ----------------
__global__ void build_h(const float* __restrict__ ea, const float* __restrict__ w,
                        const float* __restrict__ b, float* __restrict__ h) {
    int idx = blockIdx.x * blockDim.x + threadIdx.x;
    if (idx >= N_EDGES * EH) return;
    int e = idx >> 5, j = idx & 31;
    float s = b[j];
    const float* ear = ea + e * EDGE_DIM;
#pragma unroll
    for (int d = 0; d < EDGE_DIM; d++) s = fmaf(ear[d], w[d * EH + j], s);
    h[idx] = fmaxf(s, 0.f);
}

// ---------------- split-bf16 conversion of A (layer-1 input only) ----------------
__global__ void convA(const float* __restrict__ X, __nv_bfloat16* __restrict__ A3) {
    int idx = blockIdx.x * blockDim.x + threadIdx.x;
    if (idx >= N_NODES * D) return;
    int r = idx >> 7, c = idx & 127;
    float v = X[idx];
    __nv_bfloat16 hi = __float2bfloat16(v);
    __nv_bfloat16 lo = __float2bfloat16(v - __bfloat162float(hi));
    __nv_bfloat16* row = A3 + (size_t)r * KS;
    row[c] = hi; row[c + 128] = hi; row[c + 256] = lo;
}

// ---------------- B'[n, k] (K-major): permuted l2w | l2 bias | root, split ----------------
__global__ void buildB(const float* __restrict__ l2w, const float* __restrict__ b_l2,
                       const float* __restrict__ root, __nv_bfloat16* __restrict__ B3) {
    int idx = blockIdx.x * blockDim.x + threadIdx.x;   // n*128 + k
    if (idx >= NCOLS * D) return;
    int n = idx >> 7, k = idx & 127;
    float v;
    if (n < EH * D)            v = l2w[(n >> 7) * (D * D) + k * D + (n & 127)];
    else if (n < EH * D + D)   v = b_l2[k * D + (n - EH * D)];
    else                       v = root[k * D + (n - EH * D - D)];
    __nv_bfloat16 hi = __float2bfloat16(v);
    __nv_bfloat16 lo = __float2bfloat16(v - __bfloat162float(hi));
    __nv_bfloat16* row = B3 + (size_t)n * KS;
    row[k] = hi; row[k + 128] = lo; row[k + 256] = hi;
}

// ---------------- HMMA GEMM (cp.async double-buffered, fp16 output) ----------------
// Y[16384 x 4352] = A'[.,384] @ B'^T. CTA 128x128, BK=64, 8 warps (64x32 each).
__global__ void __launch_bounds__(256) gemm_mma(const __nv_bfloat16* __restrict__ A,
                                                const __nv_bfloat16* __restrict__ B,
                                                __half* __restrict__ C) {
    extern __shared__ __align__(1024) char smem[];
    const int tid = threadIdx.x, lane = tid & 31, wid = tid >> 5;
    const int warp_m = wid & 1, warp_n = wid >> 1;       // 2 x 4
    const int rowBase = blockIdx.y * BM;
    const int colBase = blockIdx.x * BN;
    const uint32_t smemU = smem_u32(smem);
    const char* Ab = (const char*)A;
    const char* Bb = (const char*)B;

    float acc[4][4][4];
#pragma unroll
    for (int i = 0; i < 4; i++)
#pragma unroll
        for (int j = 0; j < 4; j++)
#pragma unroll
            for (int r = 0; r < 4; r++) acc[i][j][r] = 0.f;

    const int ldr = tid >> 3;
    const int ldc = tid & 7;

    auto load_stage = [&](int st, int ch) {
        uint32_t sa = smemU + st * STAGE_BYTES;
        uint32_t sb = sa + BM * 128;
#pragma unroll
        for (int i = 0; i < 4; i++) {
            int r = ldr + i * 32;
            uint32_t soff = (uint32_t)(r * 128 + ((ldc * 16) ^ ((r & 7) * 16)));
            CP_ASYNC16(sa + soff, Ab + (size_t)(rowBase + r) * (KS * 2) + ch * 128 + ldc * 16);
            CP_ASYNC16(sb + soff, Bb + (size_t)(colBase + r) * (KS * 2) + ch * 128 + ldc * 16);
        }
        CP_COMMIT();
    };

    load_stage(0, 0);

    for (int ch = 0; ch < 6; ch++) {
        CP_WAIT0();
        __syncthreads();
        if (ch < 5) load_stage((ch + 1) & 1, ch + 1);

        const uint32_t aB = smemU + (ch & 1) * STAGE_BYTES;
        const uint32_t bB = aB + BM * 128;
#pragma unroll
        for (int s = 0; s < 4; s++) {
            uint32_t af[4][4], bf[4][2];
#pragma unroll
            for (int i = 0; i < 4; i++) {
                int row = warp_m * 64 + i * 16 + (lane & 15);
                int kb = s * 32 + ((lane >> 4) << 4);
                uint32_t addr = aB + row * 128 + (kb ^ ((row & 7) * 16));
                asm volatile("ldmatrix.sync.aligned.m8n8.x4.shared.b16 {%0,%1,%2,%3}, [%4];"
                             : "=r"(af[i][0]), "=r"(af[i][1]), "=r"(af[i][2]), "=r"(af[i][3])
                             : "r"(addr));
            }
#pragma unroll
            for (int j = 0; j < 4; j++) {
                int nrow = warp_n * 32 + j * 8 + (lane & 7);
                int kb = s * 32 + (((lane >> 3) & 1) << 4);
                uint32_t addr = bB + nrow * 128 + (kb ^ ((nrow & 7) * 16));
                asm volatile("ldmatrix.sync.aligned.m8n8.x2.shared.b16 {%0,%1}, [%2];"
                             : "=r"(bf[j][0]), "=r"(bf[j][1]) : "r"(addr));
            }
#pragma unroll
            for (int i = 0; i < 4; i++)
#pragma unroll
                for (int j = 0; j < 4; j++)
                    asm volatile(
                        "mma.sync.aligned.m16n8k16.row.col.f32.bf16.bf16.f32 "
                        "{%0,%1,%2,%3}, {%4,%5,%6,%7}, {%8,%9}, {%0,%1,%2,%3};"
                        : "+f"(acc[i][j][0]), "+f"(acc[i][j][1]),
                          "+f"(acc[i][j][2]), "+f"(acc[i][j][3])
                        : "r"(af[i][0]), "r"(af[i][1]), "r"(af[i][2]), "r"(af[i][3]),
                          "r"(bf[j][0]), "r"(bf[j][1]));
        }
        __syncthreads();
    }

    // Epilogue: fp16 stores (half2)
#pragma unroll
    for (int i = 0; i < 4; i++) {
        int r0 = rowBase + warp_m * 64 + i * 16 + (lane >> 2);
#pragma unroll
        for (int j = 0; j < 4; j++) {
            int col = colBase + warp_n * 32 + j * 8 + (lane & 3) * 2;
            *(__half2*)&C[(size_t)r0 * NCOLS + col] =
                __floats2half2_rn(acc[i][j][0], acc[i][j][1]);
            *(__half2*)&C[(size_t)(r0 + 8) * NCOLS + col] =
                __floats2half2_rn(acc[i][j][2], acc[i][j][3]);
        }
    }
}

// ---------------- zero acc ----------------
__global__ void zero_acc() {
    int idx = blockIdx.x * blockDim.x + threadIdx.x;
    if (idx < N_NODES * D) g_acc[idx] = 0.f;
}

// ---------------- edge message (src-sorted, fp16 gather) + scatter-add ----------------
// 64 threads per edge; each thread computes 2 output cols via half2.
__global__ void __launch_bounds__(256) edge_msg(const float* __restrict__ h,
                                                const __half* __restrict__ Y) {
    const int q = threadIdx.x >> 6;           // edge-within-block 0..3
    const int slot = blockIdx.x * 4 + q;
    const int o2 = threadIdx.x & 63;          // half2 column index
    __shared__ float sh[4][EH];
    __shared__ int se[4];
    if (o2 == 0) se[q] = g_perm[slot];
    __syncthreads();
    const int eo = se[q];
    if (o2 < EH) sh[q][o2] = h[eo * EH + o2];
    __syncthreads();
    const int src = g_idx[eo];
    const int dst = g_idx[N_EDGES + eo];
    const __half2* y2 = (const __half2*)(Y + (size_t)src * NCOLS);
    float2 b2 = __half22float2(y2[(EH * D) / 2 + o2]);    // l2-bias columns
    float mx = b2.x, my = b2.y;
#pragma unroll
    for (int k = 0; k < EH; k++) {
        float2 v = __half22float2(y2[k * 64 + o2]);
        float hk = sh[q][k];
        mx = fmaf(hk, v.x, mx);
        my = fmaf(hk, v.y, my);
    }
    atomicAdd(&g_acc[dst * D + 2 * o2], mx);
    atomicAdd(&g_acc[dst * D + 2 * o2 + 1], my);
}

// ---------------- combine: out = Yroot + acc/max(cnt,1) + bias; emit fp32 or split-A3 ----------------
__global__ void combine(const __half* __restrict__ Y, const float* __restrict__ bias,
                        float* __restrict__ outf, __nv_bfloat16* __restrict__ A3,
                        int do_relu) {
    int idx = blockIdx.x * blockDim.x + threadIdx.x;
    if (idx >= N_NODES * D) return;
    int n = idx >> 7, o = idx & 127;
    float v = __half2float(Y[(size_t)n * NCOLS + EH * D + D + o])
            + g_acc[idx] / fmaxf(g_cnt[n], 1.f) + bias[o];
    if (do_relu) v = fmaxf(v, 0.f);
    if (outf) outf[idx] = v;
    if (A3) {
        __nv_bfloat16 hi = __float2bfloat16(v);
        __nv_bfloat16 lo = __float2bfloat16(v - __bfloat162float(hi));
        __nv_bfloat16* row = A3 + (size_t)n * KS;
        row[o] = hi; row[o + 128] = hi; row[o + 256] = lo;
    }
}

// ---------------- launcher ----------------
extern "C" void kernel_launch(void* const* d_in, const int* in_sizes, int n_in,
                              void* d_out, int out_size) {
    const float* x       = (const float*)d_in[0];
    const void*  ei      = d_in[1];
    const float* ea      = (const float*)d_in[2];
    const float* w1_l1   = (const float*)d_in[3];
    const float* b1_l1   = (const float*)d_in[4];
    const float* w1_l2   = (const float*)d_in[5];
    const float* b1_l2   = (const float*)d_in[6];
    const float* w1_root = (const float*)d_in[7];
    const float* b1      = (const float*)d_in[8];
    const float* w2_l1   = (const float*)d_in[9];
    const float* b2_l1   = (const float*)d_in[10];
    const float* w2_l2   = (const float*)d_in[11];
    const float* b2_l2   = (const float*)d_in[12];
    const float* w2_root = (const float*)d_in[13];
    const float* b2      = (const float*)d_in[14];
    float*       out     = (float*)d_out;

    __half* Y;
    float *h1, *h2;
    __nv_bfloat16 *A3, *B31, *B32;
    cudaGetSymbolAddress((void**)&Y,   g_Y);
    cudaGetSymbolAddress((void**)&A3,  g_A3);
    cudaGetSymbolAddress((void**)&B31, g_B31);
    cudaGetSymbolAddress((void**)&B32, g_B32);
    cudaGetSymbolAddress((void**)&h1,  g_h1);
    cudaGetSymbolAddress((void**)&h2,  g_h2);

    const int SMEM_GEMM = 2 * STAGE_BYTES;              // 64 KB
    cudaFuncSetAttribute(gemm_mma, cudaFuncAttributeMaxDynamicSharedMemorySize, SMEM_GEMM);

    // ---- setup (indices, sort, edge MLP, weights) ----
    detect_idx<<<1, 32>>>((const long long*)ei);
    convert_idx<<<(2 * N_EDGES + 255) / 256, 256>>>(ei);
    zero_setup<<<(N_NODES + 255) / 256, 256>>>();
    count_edges<<<(N_EDGES + 255) / 256, 256>>>();
    scan_counts<<<1, 1024>>>();
    place_edges<<<(N_EDGES + 255) / 256, 256>>>();
    build_h<<<(N_EDGES * EH + 255) / 256, 256>>>(ea, w1_l1, b1_l1, h1);
    build_h<<<(N_EDGES * EH + 255) / 256, 256>>>(ea, w2_l1, b2_l1, h2);
    buildB<<<(NCOLS * D + 255) / 256, 256>>>(w1_l2, b1_l2, w1_root, B31);
    buildB<<<(NCOLS * D + 255) / 256, 256>>>(w2_l2, b2_l2, w2_root, B32);

    dim3 gGemm(NCOLS / BN, N_NODES / BM);               // (34, 128)
    const int zgrid = (N_NODES * D + 255) / 256;
    const int egrid = N_EDGES / 4;

    // ---- layer 1 ----
    convA<<<zgrid, 256>>>(x, A3);
    zero_acc<<<zgrid, 256>>>();
    gemm_mma<<<gGemm, 256, SMEM_GEMM>>>(A3, B31, Y);
    edge_msg<<<egrid, 256>>>(h1, Y);
    combine<<<zgrid, 256>>>(Y, b1, nullptr, A3, 1);
    // ---- layer 2 ----
    zero_acc<<<zgrid, 256>>>();
    gemm_mma<<<gGemm, 256, SMEM_GEMM>>>(A3, B32, Y);
    edge_msg<<<egrid, 256>>>(h2, Y);
    combine<<<zgrid, 256>>>(Y, b2, nullptr, A3, 1);
    // ---- layer 3 ----
    zero_acc<<<zgrid, 256>>>();
    gemm_mma<<<gGemm, 256, SMEM_GEMM>>>(A3, B32, Y);
    edge_msg<<<egrid, 256>>>(h2, Y);
    combine<<<zgrid, 256>>>(Y, b2, out, nullptr, 0);
}

// round 8
// speedup vs baseline: 2.9410x; 1.2468x over previous
#include <cuda_runtime.h>
#include <cuda_fp16.h>
#include <cstdint>

#define N_NODES 16384
#define N_EDGES 32768
#define D 128
#define EDGE_DIM 10
#define EH 32
#define NCOLS (EH * D + D + D)   // 4096 (L) + 128 (l2 bias) + 128 (root) = 4352
#define KS 256                   // fp16 2-term split: A=[hi|lo], B=[hi;hi]
#define BM 128
#define BN 128
#define STAGE_BYTES (BM * 128 + BN * 128)   // 32 KB per stage

// ---------------- scratch (static device globals; no allocation) ----------------
__device__ __half g_Y[N_NODES * NCOLS];    // 142 MB (fp16 Y)
__device__ __half g_A3[N_NODES * KS];
__device__ __half g_B31[NCOLS * KS];
__device__ __half g_B32[NCOLS * KS];
__device__ float g_h1[N_EDGES * EH];
__device__ float g_h2[N_EDGES * EH];
__device__ float g_acc[N_NODES * D];       // zero-init; every combine restores zero
__device__ float g_cnt[N_NODES];
__device__ int   g_idx[2 * N_EDGES];
__device__ int   g_is64;
// edge sort-by-src
__device__ int g_srcCount[N_NODES];
__device__ int g_srcOff[N_NODES];
__device__ int g_rank[N_EDGES];
__device__ int g_perm[N_EDGES];

__device__ __forceinline__ uint32_t smem_u32(const void* p) {
    uint32_t a;
    asm("{ .reg .u64 t; cvta.to.shared.u64 t, %1; cvt.u32.u64 %0, t; }" : "=r"(a) : "l"(p));
    return a;
}
#define CP_ASYNC16(saddr, gptr) \
    asm volatile("cp.async.cg.shared.global [%0], [%1], 16;" :: "r"(saddr), "l"(gptr))
#define CP_COMMIT() asm volatile("cp.async.commit_group;" ::: "memory")
#define CP_WAIT0()  asm volatile("cp.async.wait_group 0;" ::: "memory")

// ---------------- edge_index dtype detection + normalization ----------------
__global__ void detect_idx(const long long* __restrict__ ei) {
    if (threadIdx.x == 0 && blockIdx.x == 0) {
        int ok = 1;
        for (int i = 0; i < 128; i++) {
            long long v = ei[i];
            if (v < 0 || v >= N_NODES) { ok = 0; break; }
        }
        g_is64 = ok;
    }
}
__global__ void convert_idx(const void* __restrict__ ei) {
    int i = blockIdx.x * blockDim.x + threadIdx.x;
    if (i >= 2 * N_EDGES) return;
    long long v = g_is64 ? ((const long long*)ei)[i] : (long long)((const int*)ei)[i];
    int iv = (int)v;
    iv = iv < 0 ? 0 : (iv >= N_NODES ? N_NODES - 1 : iv);
    g_idx[i] = iv;
}

// ---------------- edge sorting by src + one-time dst counts ----------------
__global__ void zero_setup() {
    int i = blockIdx.x * blockDim.x + threadIdx.x;
    if (i < N_NODES) { g_srcCount[i] = 0; g_cnt[i] = 0.f; }
}
__global__ void count_edges() {
    int e = blockIdx.x * blockDim.x + threadIdx.x;
    if (e >= N_EDGES) return;
    g_rank[e] = atomicAdd(&g_srcCount[g_idx[e]], 1);
    atomicAdd(&g_cnt[g_idx[N_EDGES + e]], 1.0f);
}
__global__ void scan_counts() {          // 1 block, 1024 threads, 16 elems each
    __shared__ int part[1024];
    int t = threadIdx.x;
    int base = t * 16;
    int local[16];
    int s = 0;
#pragma unroll
    for (int i = 0; i < 16; i++) { local[i] = s; s += g_srcCount[base + i]; }
    part[t] = s;
    __syncthreads();
    for (int off = 1; off < 1024; off <<= 1) {
        int v = (t >= off) ? part[t - off] : 0;
        __syncthreads();
        part[t] += v;
        __syncthreads();
    }
    int pre = (t == 0) ? 0 : part[t - 1];
#pragma unroll
    for (int i = 0; i < 16; i++) g_srcOff[base + i] = pre + local[i];
}
__global__ void place_edges() {
    int e = blockIdx.x * blockDim.x + threadIdx.x;
    if (e >= N_EDGES) return;
    g_perm[g_srcOff[g_idx[e]] + g_rank[e]] = e;
}

// ---------------- h = relu(edge_attr @ l1w + l1b) ----------------
__global__ void build_h(const float* __restrict__ ea, const float* __restrict__ w,
                        const float* __restrict__ b, float* __restrict__ h) {
    int idx = blockIdx.x * blockDim.x + threadIdx.x;
    if (idx >= N_EDGES * EH) return;
    int e = idx >> 5, j = idx & 31;
    float s = b[j];
    const float* ear = ea + e * EDGE_DIM;
#pragma unroll
    for (int d = 0; d < EDGE_DIM; d++) s = fmaf(ear[d], w[d * EH + j], s);
    h[idx] = fmaxf(s, 0.f);
}

// ---------------- fp16 2-term split of A (layer-1 input only) ----------------
__global__ void convA(const float* __restrict__ X, __half* __restrict__ A3) {
    int idx = blockIdx.x * blockDim.x + threadIdx.x;
    if (idx >= N_NODES * D) return;
    int r = idx >> 7, c = idx & 127;
    float v = X[idx];
    __half hi = __float2half_rn(v);
    __half lo = __float2half_rn(v - __half2float(hi));
    __half* row = A3 + (size_t)r * KS;
    row[c] = hi; row[c + 128] = lo;
}

// ---------------- B'[n, k]: permuted l2w | l2 bias | root, fp16 (duplicated) ----------------
__global__ void buildB(const float* __restrict__ l2w, const float* __restrict__ b_l2,
                       const float* __restrict__ root, __half* __restrict__ B3) {
    int idx = blockIdx.x * blockDim.x + threadIdx.x;   // n*128 + k
    if (idx >= NCOLS * D) return;
    int n = idx >> 7, k = idx & 127;
    float v;
    if (n < EH * D)            v = l2w[(n >> 7) * (D * D) + k * D + (n & 127)];
    else if (n < EH * D + D)   v = b_l2[k * D + (n - EH * D)];
    else                       v = root[k * D + (n - EH * D - D)];
    __half hi = __float2half_rn(v);
    __half* row = B3 + (size_t)n * KS;
    row[k] = hi; row[k + 128] = hi;
}

// ---------------- HMMA GEMM (cp.async double-buffered, fp16 in/out) ----------------
// Y[16384 x 4352] = A'[.,256] @ B'^T. CTA 128x128, BK=64, 8 warps (64x32 each).
__global__ void __launch_bounds__(256) gemm_mma(const __half* __restrict__ A,
                                                const __half* __restrict__ B,
                                                __half* __restrict__ C) {
    extern __shared__ __align__(1024) char smem[];
    const int tid = threadIdx.x, lane = tid & 31, wid = tid >> 5;
    const int warp_m = wid & 1, warp_n = wid >> 1;       // 2 x 4
    const int rowBase = blockIdx.y * BM;
    const int colBase = blockIdx.x * BN;
    const uint32_t smemU = smem_u32(smem);
    const char* Ab = (const char*)A;
    const char* Bb = (const char*)B;

    float acc[4][4][4];
#pragma unroll
    for (int i = 0; i < 4; i++)
#pragma unroll
        for (int j = 0; j < 4; j++)
#pragma unroll
            for (int r = 0; r < 4; r++) acc[i][j][r] = 0.f;

    const int ldr = tid >> 3;
    const int ldc = tid & 7;

    auto load_stage = [&](int st, int ch) {
        uint32_t sa = smemU + st * STAGE_BYTES;
        uint32_t sb = sa + BM * 128;
#pragma unroll
        for (int i = 0; i < 4; i++) {
            int r = ldr + i * 32;
            uint32_t soff = (uint32_t)(r * 128 + ((ldc * 16) ^ ((r & 7) * 16)));
            CP_ASYNC16(sa + soff, Ab + (size_t)(rowBase + r) * (KS * 2) + ch * 128 + ldc * 16);
            CP_ASYNC16(sb + soff, Bb + (size_t)(colBase + r) * (KS * 2) + ch * 128 + ldc * 16);
        }
        CP_COMMIT();
    };

    load_stage(0, 0);

    for (int ch = 0; ch < 4; ch++) {               // K = 256 = 4 chunks of 64
        CP_WAIT0();
        __syncthreads();
        if (ch < 3) load_stage((ch + 1) & 1, ch + 1);

        const uint32_t aB = smemU + (ch & 1) * STAGE_BYTES;
        const uint32_t bB = aB + BM * 128;
#pragma unroll
        for (int s = 0; s < 4; s++) {
            uint32_t af[4][4], bf[4][2];
#pragma unroll
            for (int i = 0; i < 4; i++) {
                int row = warp_m * 64 + i * 16 + (lane & 15);
                int kb = s * 32 + ((lane >> 4) << 4);
                uint32_t addr = aB + row * 128 + (kb ^ ((row & 7) * 16));
                asm volatile("ldmatrix.sync.aligned.m8n8.x4.shared.b16 {%0,%1,%2,%3}, [%4];"
                             : "=r"(af[i][0]), "=r"(af[i][1]), "=r"(af[i][2]), "=r"(af[i][3])
                             : "r"(addr));
            }
#pragma unroll
            for (int j = 0; j < 4; j++) {
                int nrow = warp_n * 32 + j * 8 + (lane & 7);
                int kb = s * 32 + (((lane >> 3) & 1) << 4);
                uint32_t addr = bB + nrow * 128 + (kb ^ ((nrow & 7) * 16));
                asm volatile("ldmatrix.sync.aligned.m8n8.x2.shared.b16 {%0,%1}, [%2];"
                             : "=r"(bf[j][0]), "=r"(bf[j][1]) : "r"(addr));
            }
#pragma unroll
            for (int i = 0; i < 4; i++)
#pragma unroll
                for (int j = 0; j < 4; j++)
                    asm volatile(
                        "mma.sync.aligned.m16n8k16.row.col.f32.f16.f16.f32 "
                        "{%0,%1,%2,%3}, {%4,%5,%6,%7}, {%8,%9}, {%0,%1,%2,%3};"
                        : "+f"(acc[i][j][0]), "+f"(acc[i][j][1]),
                          "+f"(acc[i][j][2]), "+f"(acc[i][j][3])
                        : "r"(af[i][0]), "r"(af[i][1]), "r"(af[i][2]), "r"(af[i][3]),
                          "r"(bf[j][0]), "r"(bf[j][1]));
        }
        __syncthreads();
    }

    // Epilogue: fp16 stores (half2)
#pragma unroll
    for (int i = 0; i < 4; i++) {
        int r0 = rowBase + warp_m * 64 + i * 16 + (lane >> 2);
#pragma unroll
        for (int j = 0; j < 4; j++) {
            int col = colBase + warp_n * 32 + j * 8 + (lane & 3) * 2;
            *(__half2*)&C[(size_t)r0 * NCOLS + col] =
                __floats2half2_rn(acc[i][j][0], acc[i][j][1]);
            *(__half2*)&C[(size_t)(r0 + 8) * NCOLS + col] =
                __floats2half2_rn(acc[i][j][2], acc[i][j][3]);
        }
    }
}

// ---------------- edge message (src-sorted, fp16 gather) + scatter-add ----------------
// 64 threads per edge; each thread computes 2 output cols via half2.
__global__ void __launch_bounds__(256) edge_msg(const float* __restrict__ h,
                                                const __half* __restrict__ Y) {
    const int q = threadIdx.x >> 6;           // edge-within-block 0..3
    const int slot = blockIdx.x * 4 + q;
    const int o2 = threadIdx.x & 63;          // half2 column index
    __shared__ float sh[4][EH];
    __shared__ int se[4];
    if (o2 == 0) se[q] = g_perm[slot];
    __syncthreads();
    const int eo = se[q];
    if (o2 < EH) sh[q][o2] = h[eo * EH + o2];
    __syncthreads();
    const int src = g_idx[eo];
    const int dst = g_idx[N_EDGES + eo];
    const __half2* y2 = (const __half2*)(Y + (size_t)src * NCOLS);
    float2 b2 = __half22float2(y2[(EH * D) / 2 + o2]);    // l2-bias columns
    float mx = b2.x, my = b2.y;
#pragma unroll
    for (int k = 0; k < EH; k++) {
        float2 v = __half22float2(y2[k * 64 + o2]);
        float hk = sh[q][k];
        mx = fmaf(hk, v.x, mx);
        my = fmaf(hk, v.y, my);
    }
    atomicAdd(&g_acc[dst * D + 2 * o2], mx);
    atomicAdd(&g_acc[dst * D + 2 * o2 + 1], my);
}

// ---------------- combine: out = Yroot + acc/max(cnt,1) + bias; resets acc to 0 ----------------
__global__ void combine(const __half* __restrict__ Y, const float* __restrict__ bias,
                        float* __restrict__ outf, __half* __restrict__ A3,
                        int do_relu) {
    int idx = blockIdx.x * blockDim.x + threadIdx.x;
    if (idx >= N_NODES * D) return;
    int n = idx >> 7, o = idx & 127;
    float v = __half2float(Y[(size_t)n * NCOLS + EH * D + D + o])
            + g_acc[idx] / fmaxf(g_cnt[n], 1.f) + bias[o];
    g_acc[idx] = 0.f;                         // reset for next layer / next replay
    if (do_relu) v = fmaxf(v, 0.f);
    if (outf) outf[idx] = v;
    if (A3) {
        __half hi = __float2half_rn(v);
        __half lo = __float2half_rn(v - __half2float(hi));
        __half* row = A3 + (size_t)n * KS;
        row[o] = hi; row[o + 128] = lo;
    }
}

// ---------------- launcher ----------------
extern "C" void kernel_launch(void* const* d_in, const int* in_sizes, int n_in,
                              void* d_out, int out_size) {
    const float* x       = (const float*)d_in[0];
    const void*  ei      = d_in[1];
    const float* ea      = (const float*)d_in[2];
    const float* w1_l1   = (const float*)d_in[3];
    const float* b1_l1   = (const float*)d_in[4];
    const float* w1_l2   = (const float*)d_in[5];
    const float* b1_l2   = (const float*)d_in[6];
    const float* w1_root = (const float*)d_in[7];
    const float* b1      = (const float*)d_in[8];
    const float* w2_l1   = (const float*)d_in[9];
    const float* b2_l1   = (const float*)d_in[10];
    const float* w2_l2   = (const float*)d_in[11];
    const float* b2_l2   = (const float*)d_in[12];
    const float* w2_root = (const float*)d_in[13];
    const float* b2      = (const float*)d_in[14];
    float*       out     = (float*)d_out;

    __half *Y, *A3, *B31, *B32;
    float *h1, *h2;
    cudaGetSymbolAddress((void**)&Y,   g_Y);
    cudaGetSymbolAddress((void**)&A3,  g_A3);
    cudaGetSymbolAddress((void**)&B31, g_B31);
    cudaGetSymbolAddress((void**)&B32, g_B32);
    cudaGetSymbolAddress((void**)&h1,  g_h1);
    cudaGetSymbolAddress((void**)&h2,  g_h2);

    const int SMEM_GEMM = 2 * STAGE_BYTES;              // 64 KB
    cudaFuncSetAttribute(gemm_mma, cudaFuncAttributeMaxDynamicSharedMemorySize, SMEM_GEMM);

    // ---- setup (indices, sort, edge MLP, weights) ----
    detect_idx<<<1, 32>>>((const long long*)ei);
    convert_idx<<<(2 * N_EDGES + 255) / 256, 256>>>(ei);
    zero_setup<<<(N_NODES + 255) / 256, 256>>>();
    count_edges<<<(N_EDGES + 255) / 256, 256>>>();
    scan_counts<<<1, 1024>>>();
    place_edges<<<(N_EDGES + 255) / 256, 256>>>();
    build_h<<<(N_EDGES * EH + 255) / 256, 256>>>(ea, w1_l1, b1_l1, h1);
    build_h<<<(N_EDGES * EH + 255) / 256, 256>>>(ea, w2_l1, b2_l1, h2);
    buildB<<<(NCOLS * D + 255) / 256, 256>>>(w1_l2, b1_l2, w1_root, B31);
    buildB<<<(NCOLS * D + 255) / 256, 256>>>(w2_l2, b2_l2, w2_root, B32);

    dim3 gGemm(NCOLS / BN, N_NODES / BM);               // (34, 128)
    const int zgrid = (N_NODES * D + 255) / 256;
    const int egrid = N_EDGES / 4;

    // ---- layer 1 ----
    convA<<<zgrid, 256>>>(x, A3);
    gemm_mma<<<gGemm, 256, SMEM_GEMM>>>(A3, B31, Y);
    edge_msg<<<egrid, 256>>>(h1, Y);
    combine<<<zgrid, 256>>>(Y, b1, nullptr, A3, 1);
    // ---- layer 2 ----
    gemm_mma<<<gGemm, 256, SMEM_GEMM>>>(A3, B32, Y);
    edge_msg<<<egrid, 256>>>(h2, Y);
    combine<<<zgrid, 256>>>(Y, b2, nullptr, A3, 1);
    // ---- layer 3 ----
    gemm_mma<<<gGemm, 256, SMEM_GEMM>>>(A3, B32, Y);
    edge_msg<<<egrid, 256>>>(h2, Y);
    combine<<<zgrid, 256>>>(Y, b2, out, nullptr, 0);
}